// round 17
// baseline (speedup 1.0000x reference)
#include <cuda_runtime.h>
#include <cuda_fp16.h>
#include <math.h>
#include <stdint.h>

#define BB   128
#define TT   24
#define EE   512
#define HH   512
#define VV   10000
#define G4   2048
#define BTR  3072
#define OUTROW 250000
#define NPAD 10112          // 79 * 128  (padded vocab rows)
#define RNN_BLOCKS 32
#define NSTART   16                      // output-init items
#define NXG      (TT * 16)               // 384 Xg tiles
#define NTILES_N 79
#define NLOG     (TT * NTILES_N)         // 1896 logits tiles
#define NT_TOT   (NSTART + NXG + NLOG)   // 2296
#define NTHREADS 1024

// ---------------- device scratch (no allocations allowed) ----------------
__device__ __half g_X   [BTR * EE];        // embedded captions (fp16)
__device__ __half g_Wih [G4 * EE];         // permuted W_ih (fp16)
__device__ __half g_Whh [G4 * HH];         // permuted W_hh (fp16)
__device__ __half g_Wout[NPAD * HH];       // padded W_out (fp16)
__device__ __half g_Hall[BTR * HH];        // all hidden states (fp16)
__device__ __half g_hA  [BB * HH];
__device__ __half g_hB  [BB * HH];
__device__ float  g_c   [BB * HH];
__device__ float  g_bias[G4];              // permuted b_ih+b_hh
__device__ float  g_Xg  [BTR * G4];        // input gates (permuted cols)
__device__ int    g_ctr;                   // recurrence step counter
__device__ int    g_tile;                  // global work queue
__device__ int    g_xg_done[TT];           // per-step Xg tile completion

// ---------------- small helpers ----------------
__device__ __forceinline__ float sigf(float x) { return 1.0f / (1.0f + expf(-x)); }

__device__ __forceinline__ uint32_t smem_to_u32(const void* p) {
    uint32_t a;
    asm("{ .reg .u64 t; cvta.to.shared.u64 t, %1; cvt.u32.u64 %0, t; }" : "=r"(a) : "l"(p));
    return a;
}

// ---------------- warp-level tensor ops (sm_80+ PTX; legal on plain sm_103) ----
__device__ __forceinline__ void ldsm_x4(uint32_t* r, uint32_t addr) {
    asm volatile("ldmatrix.sync.aligned.m8n8.x4.shared.b16 {%0,%1,%2,%3}, [%4];"
                 : "=r"(r[0]), "=r"(r[1]), "=r"(r[2]), "=r"(r[3]) : "r"(addr));
}

__device__ __forceinline__ void mma_f16(float* c, const uint32_t* a, const uint32_t* b) {
    asm volatile(
        "mma.sync.aligned.m16n8k16.row.col.f32.f16.f16.f32 "
        "{%0,%1,%2,%3}, {%4,%5,%6,%7}, {%8,%9}, {%0,%1,%2,%3};"
        : "+f"(c[0]), "+f"(c[1]), "+f"(c[2]), "+f"(c[3])
        : "r"(a[0]), "r"(a[1]), "r"(a[2]), "r"(a[3]), "r"(b[0]), "r"(b[1]));
}

// ---------------- cp.async (sm_80+ PTX) ----------------
__device__ __forceinline__ void cp_async16(uint32_t dst, const void* src) {
    asm volatile("cp.async.cg.shared.global [%0], [%1], 16;" :: "r"(dst), "l"(src));
}
#define CP_COMMIT() asm volatile("cp.async.commit_group;" ::: "memory")
// Last K-tile's data is the NEWEST committed group -> drain all; otherwise the
// next prefetch may remain in flight.
__device__ __forceinline__ void cp_wait(bool last) {
    if (last) asm volatile("cp.async.wait_group 0;" ::: "memory");
    else      asm volatile("cp.async.wait_group 1;" ::: "memory");
}

// ---------------- smem layout ----------------
// Plane = 128 rows x 64 fp16 k, rows padded to 144B (36 words; 36%32==4 =>
// ldmatrix phases conflict-free). Worker path: 3 stages of (A+B). RNN path:
// persistent Whh slice (64 x 512, rows padded to 1040B) + 3 h stages.
#define TILE_B   (128 * 144)
#define SM_A     0
#define SM_B     (1 * TILE_B)
#define STAGE_B  (2 * TILE_B)              // 36864
#define RW_ROW   1040
#define RSM_W    0                         // 64*1040 = 66560
#define RSM_H0   (64 * RW_ROW)
#define SMEM_FUSED (RSM_H0 + 3 * TILE_B)   // 121856

// Async-load one 128x64 fp16 tile (gmem ld = 512) into padded smem rows.
// 1024 groups of 8 fp16 -> exactly one cp.async per thread.
__device__ __forceinline__ void load_tile_async(uint32_t dst, const __half* src,
                                                int row0, int k0, int tid) {
    int r  = tid >> 3;                 // 0..127
    int k8 = (tid & 7) << 3;           // 0..56
    cp_async16(dst + r * 144 + k8 * 2,
               src + (size_t)(row0 + r) * 512 + k0 + k8);
}

__device__ __forceinline__ void load_stage(uint32_t stage,
        const __half* A, int arow0, const __half* Bm, int brow0,
        int k0, int tid) {
    load_tile_async(stage + SM_A, A, arow0, k0, tid);
    load_tile_async(stage + SM_B, Bm, brow0, k0, tid);
    CP_COMMIT();
}

// ---------------- GEMM mainloop: 3-stage pipeline, ONE sync per K-tile --------
// acc[ni][4] += A[128xK] @ B[128xK]^T (fp16 in, fp32 acc). 32 warps =
// 8(m) x 4(n); warp tile 16m x 32n; K = 512 in 8 tiles of 64.
__device__ __forceinline__ void gemm_mainloop(char* sm,
        const __half* A, int arow0, const __half* Bm, int brow0,
        float acc[4][4]) {
    const int tid  = threadIdx.x;
    const int lane = tid & 31;
    const int w    = tid >> 5;
    const int wm   = w & 7;            // 0..7  (m-group of 16 rows)
    const int wn   = w >> 3;           // 0..3  (n-group of 32 cols)
    const uint32_t sb = smem_to_u32(sm);

    const int lrow = lane & 15;
    const int lcol = (lane >> 4) * 16;

    load_stage(sb,           A, arow0, Bm, brow0, 0,  tid);
    load_stage(sb + STAGE_B, A, arow0, Bm, brow0, 64, tid);

    for (int kt = 0; kt < 8; kt++) {
        const uint32_t cur = sb + (kt % 3) * STAGE_B;
        cp_wait(kt == 7);
        __syncthreads();
        if (kt + 2 < 8)
            load_stage(sb + ((kt + 2) % 3) * STAGE_B,
                       A, arow0, Bm, brow0, (kt + 2) * 64, tid);

#pragma unroll
        for (int kc = 0; kc < 4; kc++) {
            uint32_t ah[4], bh[4][2];
            {
                uint32_t a = cur + SM_A + (wm * 16 + lrow) * 144 + kc * 32 + lcol;
                ldsm_x4(ah, a);
            }
#pragma unroll
            for (int n2 = 0; n2 < 2; n2++) {
                uint32_t r0[4];
                uint32_t b = cur + SM_B + (wn * 32 + n2 * 16 + lrow) * 144 + kc * 32 + lcol;
                ldsm_x4(r0, b);
                bh[n2 * 2 + 0][0] = r0[0]; bh[n2 * 2 + 0][1] = r0[2];
                bh[n2 * 2 + 1][0] = r0[1]; bh[n2 * 2 + 1][1] = r0[3];
            }
#pragma unroll
            for (int ni = 0; ni < 4; ni++)
                mma_f16(acc[ni], ah, bh[ni]);
        }
    }
}

// ---------------- fused persistent kernel: EVERYTHING post-prep ----------------
// Blocks 0..31: LSTM recurrence (smem-resident Whh slice, 3-stage h pipeline,
//   per-step Xg gate + arrive on g_ctr). 32 warps = 8(m) x 4(n), warp 16m x 16n.
// All blocks (workers immediately, rnn blocks afterwards) drain the queue:
//   [0,16):        output init (one-hot t=0 rows; item 0 also writes the tail)
//   [16,400):      Xg tiles, t-major; completion counted in g_xg_done[t]
//   [400,2296):    logits tiles, gated on g_ctr >= 32*(t+1)
__global__ __launch_bounds__(NTHREADS, 1)
void fused_all(const float* __restrict__ bout, float* __restrict__ out,
               const int* __restrict__ clen, int extra) {
    extern __shared__ char sm[];
    const uint32_t sb = smem_to_u32(sm);
    const int tid  = threadIdx.x;
    const int lane = tid & 31;
    const int w    = tid >> 5;
    const int wm   = w & 7, wn = w >> 3;
    const int tpar = lane & 1;
    const int lrow = lane & 15;
    const int lcol = (lane >> 4) * 16;

    if (blockIdx.x < RNN_BLOCKS) {
        const int jb = blockIdx.x;

        // persistent Whh slice: 64 rows x 512 cols (4096 groups of 8)
#pragma unroll
        for (int i = 0; i < 4; i++) {
            int e  = tid + i * NTHREADS;
            int r  = e >> 6;
            int k8 = (e & 63) << 3;
            cp_async16(sb + RSM_W + r * RW_ROW + k8 * 2,
                       g_Whh + (size_t)(jb * 64 + r) * 512 + k8);
        }
        CP_COMMIT();

        for (int t = 0; t < TT; t++) {
            const __half* hin  = (t & 1) ? g_hB : g_hA;
            __half*       hout = (t & 1) ? g_hA : g_hB;

            load_tile_async(sb + RSM_H0,          hin, 0, 0,  tid); CP_COMMIT();
            load_tile_async(sb + RSM_H0 + TILE_B, hin, 0, 64, tid); CP_COMMIT();

            float acc[2][4];
#pragma unroll
            for (int b = 0; b < 2; b++)
#pragma unroll
                for (int c = 0; c < 4; c++) acc[b][c] = 0.0f;

            for (int kt = 0; kt < 8; kt++) {
                const uint32_t curH = sb + RSM_H0 + (kt % 3) * TILE_B;
                cp_wait(kt == 7);
                __syncthreads();
                if (kt + 2 < 8) {
                    load_tile_async(sb + RSM_H0 + ((kt + 2) % 3) * TILE_B,
                                    hin, 0, (kt + 2) * 64, tid);
                    CP_COMMIT();
                }

#pragma unroll
                for (int kc = 0; kc < 4; kc++) {
                    uint32_t ah[4], bh[2][2];
                    {
                        uint32_t a = curH + (wm * 16 + lrow) * 144 + kc * 32 + lcol;
                        ldsm_x4(ah, a);
                    }
                    {
                        uint32_t r0[4];
                        uint32_t b = sb + RSM_W + (wn * 16 + lrow) * RW_ROW
                                   + kt * 128 + kc * 32 + lcol;
                        ldsm_x4(r0, b);
                        bh[0][0] = r0[0]; bh[0][1] = r0[2];
                        bh[1][0] = r0[1]; bh[1][1] = r0[3];
                    }
#pragma unroll
                    for (int ni = 0; ni < 2; ni++)
                        mma_f16(acc[ni], ah, bh[ni]);
                }
            }

            // gate: all 16 Xg tiles of step t must be published
            if (tid == 0) {
                while (atomicAdd(&g_xg_done[t], 0) < 16) __nanosleep(32);
                __threadfence();
            }
            __syncthreads();

            // cell epilogue
#pragma unroll
            for (int ni = 0; ni < 2; ni++) {
                int m = wm * 16 + (lane >> 2);
                int n = jb * 64 + wn * 16 + ni * 8 + (lane & 3) * 2;
                int r = t * 128 + m;
                const float* xg = g_Xg + (size_t)r * G4;

                float c0 = acc[ni][0] + xg[n];
                float c1 = acc[ni][1] + xg[n + 1];
                float c2 = acc[ni][2] + xg[8 * G4 + n];
                float c3 = acc[ni][3] + xg[8 * G4 + n + 1];

                float e0 = __shfl_xor_sync(0xFFFFFFFFu, c0, 1);
                float e1 = __shfl_xor_sync(0xFFFFFFFFu, c1, 1);
                float e2 = __shfl_xor_sync(0xFFFFFFFFu, c2, 1);
                float e3 = __shfl_xor_sync(0xFFFFFFFFu, c3, 1);

                int   row, j = n >> 2;
                float iv, fv, gv, ov;
                if (!tpar) { row = m;     iv = c0; fv = c1; gv = e0; ov = e1; }
                else       { row = m + 8; iv = e2; fv = e3; gv = c2; ov = c3; }

                float cO = g_c[row * HH + j];
                float cN = sigf(fv) * cO + sigf(iv) * tanhf(gv);
                float hN = sigf(ov) * tanhf(cN);
                g_c[row * HH + j] = cN;

                __half hh = __float2half(hN);
                hout[row * HH + j] = hh;
                g_Hall[(size_t)(t * 128 + row) * HH + j] = hh;
            }

            __threadfence();            // publish h + Hall (all threads)
            __syncthreads();
            if (tid == 0) {
                atomicAdd(&g_ctr, 1);
                if (t + 1 < TT) {
                    int target = RNN_BLOCKS * (t + 1);
                    while (atomicAdd(&g_ctr, 0) < target) { }
                }
            }
            __syncthreads();
        }
    }

    // ---------------- work-queue loop (all blocks) ----------------
    __shared__ int s_q;
    for (;;) {
        __syncthreads();
        if (tid == 0) s_q = atomicAdd(&g_tile, 1);
        __syncthreads();
        int q = s_q;
        if (q >= NT_TOT) break;

        if (q < NSTART) {
            // output init: 8 batch rows of the t=0 one-hot; item 0 also the tail
            int b0 = q * 8;
            for (int idx = tid; idx < 8 * VV; idx += NTHREADS) {
                int br = idx / VV, v = idx - br * VV;
                out[(size_t)(b0 + br) * OUTROW + v] = (v == 1) ? 1.0f : 0.0f;
            }
            if (q == 0)
                for (int idx = tid; idx < extra; idx += NTHREADS)
                    out[(size_t)BB * OUTROW + idx] =
                        (idx < BB) ? (float)(clen[idx] - 1) : 0.0f;
            continue;
        }

        if (q < NSTART + NXG) {
            // Xg tile: t-major so step-t tiles come off the queue first
            int idx = q - NSTART;
            int t = idx >> 4, nb = idx & 15;

            float acc[4][4];
#pragma unroll
            for (int b = 0; b < 4; b++)
#pragma unroll
                for (int c = 0; c < 4; c++) acc[b][c] = 0.0f;

            gemm_mainloop(sm, g_X, t * 128, g_Wih, nb * 128, acc);

#pragma unroll
            for (int ni = 0; ni < 4; ni++) {
                int m = t * 128 + wm * 16 + (lane >> 2);
                int n = nb * 128 + wn * 32 + ni * 8 + (lane & 3) * 2;
                g_Xg[(size_t)m * G4 + n]           = acc[ni][0] + g_bias[n];
                g_Xg[(size_t)m * G4 + n + 1]       = acc[ni][1] + g_bias[n + 1];
                g_Xg[(size_t)(m + 8) * G4 + n]     = acc[ni][2] + g_bias[n];
                g_Xg[(size_t)(m + 8) * G4 + n + 1] = acc[ni][3] + g_bias[n + 1];
            }
            __threadfence();
            __syncthreads();
            if (tid == 0) atomicAdd(&g_xg_done[t], 1);
            continue;
        }

        // logits tile
        int idx = q - NSTART - NXG;
        int t  = idx / NTILES_N;
        int nb = idx - t * NTILES_N;

        if (tid == 0) {
            int target = RNN_BLOCKS * (t + 1);
            while (atomicAdd(&g_ctr, 0) < target) __nanosleep(64);
            __threadfence();
        }
        __syncthreads();

        float acc[4][4];
#pragma unroll
        for (int b = 0; b < 4; b++)
#pragma unroll
            for (int c = 0; c < 4; c++) acc[b][c] = 0.0f;

        gemm_mainloop(sm, g_Hall, t * 128, g_Wout, nb * 128, acc);

#pragma unroll
        for (int ni = 0; ni < 4; ni++) {
            int b0 = wm * 16 + (lane >> 2);
            int n  = nb * 128 + wn * 32 + ni * 8 + (lane & 3) * 2;
            float* d0 = out + (size_t)b0 * OUTROW + (size_t)(t + 1) * VV;
            float* d1 = out + (size_t)(b0 + 8) * OUTROW + (size_t)(t + 1) * VV;
            if (n < VV) {
                d0[n] = acc[ni][0] + bout[n];
                d1[n] = acc[ni][2] + bout[n];
            }
            if (n + 1 < VV) {
                d0[n + 1] = acc[ni][1] + bout[n + 1];
                d1[n + 1] = acc[ni][3] + bout[n + 1];
            }
        }
    }
}

// ---------------- merged prep kernel --------------------------------------
#define POFF1 (BB * HH)                    // 65536   hA / c
#define POFF2 (POFF1 + G4)                 // 67584   bias
#define POFF3 (POFF2 + BTR * 128)          // 460800  embed (float4 groups)
#define POFF4 (POFF3 + G4 * 128)           // 722944  Wih split
#define POFF5 (POFF4 + G4 * 128)           // 985088  Whh split
#define PTOT  (POFF5 + NPAD * 128)         // 2279424 Wout split

__global__ void k_prep(const float* __restrict__ img,
                       const float* __restrict__ bih, const float* __restrict__ bhh,
                       const int* __restrict__ caps, const float* __restrict__ Wemb,
                       const float* __restrict__ Wih, const float* __restrict__ Whh,
                       const float* __restrict__ Wout) {
    int i = blockIdx.x * blockDim.x + threadIdx.x;
    if (i == 0) {
        g_ctr = 0; g_tile = 0;
        for (int t = 0; t < TT; t++) g_xg_done[t] = 0;
    }
    if (i < POFF1) {
        g_hA[i] = __float2half(img[i]);
        g_c[i] = 0.0f;
        return;
    }
    if (i < POFF2) {                       // permuted bias: rp=j*4+g <- g*512+j
        int p = i - POFF1;
        int j = p >> 2, g = p & 3;
        g_bias[p] = bih[g * HH + j] + bhh[g * HH + j];
        return;
    }
    if (i < POFF3) {                       // embedding, float4 groups
        int p = i - POFF2;
        int e4 = p & 127, r = p >> 7;
        int t = r >> 7, b = r & 127;
        int tok = caps[b * TT + t];
        float4 v = make_float4(0.f, 0.f, 0.f, 0.f);
        if (tok != 0) v = *(const float4*)(Wemb + (size_t)tok * EE + e4 * 4);
        int base = r * EE + e4 * 4;
        g_X[base + 0] = __float2half(v.x);
        g_X[base + 1] = __float2half(v.y);
        g_X[base + 2] = __float2half(v.z);
        g_X[base + 3] = __float2half(v.w);
        return;
    }
    if (i < POFF5) {                       // Wih / Whh permuted split
        int p = (i < POFF4) ? (i - POFF3) : (i - POFF4);
        const float* W = (i < POFF4) ? Wih : Whh;
        __half* dst = (i < POFF4) ? g_Wih : g_Whh;
        int k4 = p & 127, rp = p >> 7;
        int j = rp >> 2, g = rp & 3;
        float4 v = *(const float4*)(W + (size_t)(g * HH + j) * 512 + k4 * 4);
        int base = rp * 512 + k4 * 4;
        dst[base + 0] = __float2half(v.x);
        dst[base + 1] = __float2half(v.y);
        dst[base + 2] = __float2half(v.z);
        dst[base + 3] = __float2half(v.w);
        return;
    }
    if (i < PTOT) {                        // Wout (zero-padded to NPAD rows)
        int p = i - POFF5;
        int k4 = p & 127, r = p >> 7;
        float4 v = make_float4(0.f, 0.f, 0.f, 0.f);
        if (r < VV) v = *(const float4*)(Wout + (size_t)r * HH + k4 * 4);
        int base = r * 512 + k4 * 4;
        g_Wout[base + 0] = __float2half(v.x);
        g_Wout[base + 1] = __float2half(v.y);
        g_Wout[base + 2] = __float2half(v.z);
        g_Wout[base + 3] = __float2half(v.w);
    }
}

// ---------------- launch ----------------
extern "C" void kernel_launch(void* const* d_in, const int* in_sizes, int n_in,
                              void* d_out, int out_size) {
    const float* images = (const float*)d_in[0];
    const int*   caps   = (const int*)  d_in[1];
    const int*   clen   = (const int*)  d_in[2];
    const float* Wemb   = (const float*)d_in[3];
    const float* Wih    = (const float*)d_in[4];
    const float* Whh    = (const float*)d_in[5];
    const float* bih    = (const float*)d_in[6];
    const float* bhh    = (const float*)d_in[7];
    const float* Wout   = (const float*)d_in[8];
    const float* bout   = (const float*)d_in[9];
    float* out = (float*)d_out;

    cudaFuncSetAttribute(fused_all, cudaFuncAttributeMaxDynamicSharedMemorySize, SMEM_FUSED);

    // Fused grid: all blocks must be co-resident (workers spin on counters).
    int nper = 1;
    cudaOccupancyMaxActiveBlocksPerMultiprocessor(&nper, fused_all, NTHREADS, SMEM_FUSED);
    if (nper < 1) nper = 1;
    int nsm = 148;
    cudaDeviceGetAttribute(&nsm, cudaDevAttrMultiProcessorCount, 0);
    int fused_grid = nsm * nper;
    if (fused_grid < RNN_BLOCKS + 1) fused_grid = RNN_BLOCKS + 1;

    int extra = out_size - BB * OUTROW;
    if (extra < 0) extra = 0;

    // 1. single merged prep launch
    k_prep<<<(PTOT + 255) / 256, 256>>>(images, bih, bhh, caps, Wemb, Wih, Whh, Wout);

    // 2. everything else: one persistent kernel
    fused_all<<<fused_grid, NTHREADS, SMEM_FUSED>>>(bout, out, clen, extra);
}